// round 1
// baseline (speedup 1.0000x reference)
#include <cuda_runtime.h>

#define NN 100000
#define NE 640000
#define HH 128
#define NU 1000

// ---------------- scratch (static device memory; no runtime allocs) ----------------
__device__ float g_bufA[(size_t)NN * HH];   // 51.2 MB
__device__ float g_bufB[(size_t)NN * HH];   // 51.2 MB
__device__ float g_deg[NN];                 // deg -> deg^-1/2 in place
__device__ float g_norm[NE];
__device__ int   g_is64;                    // edge_index dtype flag (1 = int64)

// ---------------- dtype sniffing: int64 vs int32 edge_index ----------------
// If int64 (values < 100000), every odd 32-bit word of the buffer is 0.
__global__ void sniff_dtype_kernel(const int* __restrict__ ei32) {
    if (threadIdx.x == 0 && blockIdx.x == 0) {
        int all_zero = 1;
        for (int i = 0; i < 256; i++) {
            if (ei32[2 * i + 1] != 0) { all_zero = 0; break; }
        }
        g_is64 = all_zero;
    }
}

__device__ __forceinline__ int edge_idx(const void* ei, int pos) {
    if (g_is64) return (int)((const long long*)ei)[pos];
    return ((const int*)ei)[pos];
}

// ---------------- small prep kernels ----------------
__global__ void zero_deg_kernel(float* deg) {
    int i = blockIdx.x * blockDim.x + threadIdx.x;
    if (i < NN) deg[i] = 0.f;
}

__global__ void deg_kernel(const void* __restrict__ ei, const float* __restrict__ w, float* deg) {
    int e = blockIdx.x * blockDim.x + threadIdx.x;
    if (e < NE) {
        int c = edge_idx(ei, NE + e);   // col = edge_index[1][e]
        atomicAdd(deg + c, w[e]);
    }
}

__global__ void dinv_kernel(float* deg) {
    int i = blockIdx.x * blockDim.x + threadIdx.x;
    if (i < NN) {
        float d = deg[i];
        deg[i] = (d > 0.f) ? rsqrtf(fmaxf(d, 1e-30f)) : 0.f;
    }
}

__global__ void norm_kernel(const void* __restrict__ ei, const float* __restrict__ w,
                            const float* __restrict__ dinv, float* __restrict__ nrm) {
    int e = blockIdx.x * blockDim.x + threadIdx.x;
    if (e < NE) {
        int r = edge_idx(ei, e);
        int c = edge_idx(ei, NE + e);
        nrm[e] = dinv[r] * w[e] * dinv[c];
    }
}

__global__ void init_bias_kernel(float* __restrict__ buf, const float* __restrict__ bias) {
    int i = blockIdx.x * blockDim.x + threadIdx.x;
    if (i < NN * HH) buf[i] = bias[i & (HH - 1)];
}

// ---------------- edge scatter: agg[col] += norm * h[row] ----------------
// 1 warp per edge; each lane moves 4 floats with a single vector reduction.
__global__ void scatter_kernel(const void* __restrict__ ei, const float* __restrict__ nrm,
                               const float* __restrict__ h, float* __restrict__ agg) {
    int idx = blockIdx.x * blockDim.x + threadIdx.x;
    int e = idx >> 5;
    if (e >= NE) return;
    int lane = idx & 31;
    int r = edge_idx(ei, e);
    int c = edge_idx(ei, NE + e);
    float nw = __ldg(nrm + e);
    float4 v = *reinterpret_cast<const float4*>(h + (size_t)r * HH + lane * 4);
    v.x *= nw; v.y *= nw; v.z *= nw; v.w *= nw;
    float* dst = agg + (size_t)c * HH + lane * 4;
    asm volatile("red.global.add.v4.f32 [%0], {%1,%2,%3,%4};"
                 :: "l"(dst), "f"(v.x), "f"(v.y), "f"(v.z), "f"(v.w)
                 : "memory");
}

// ---------------- fp32 GEMM, K fixed at 128: C[M,N] = A[M,128] @ B[128,N] (+bias) ----------------
// 128x128 block tile, 256 threads, 8x8 per-thread micro-tile.
// As padded to 129 floats/row -> conflict-free scalar A reads in the k-loop.
#define GEMM_SMEM ((128 * 129 + 128 * 128) * 4)

__global__ void __launch_bounds__(256, 1)
gemm_k128(const float* __restrict__ A, const float* __restrict__ B,
          const float* __restrict__ bias, float* __restrict__ C,
          int M, int N) {
    extern __shared__ float sm[];
    float* As = sm;               // As[m*129 + k]
    float* Bs = sm + 128 * 129;   // Bs[k*128 + n]

    const int t    = threadIdx.x;
    const int row0 = blockIdx.x * 128;
    const int col0 = blockIdx.y * 128;

    // Load A tile (rows row0..row0+127, full K=128), coalesced float4.
    #pragma unroll
    for (int i = 0; i < 16; i++) {
        int idx = t + i * 256;        // 0..4095
        int m   = idx >> 5;           // 0..127
        int k   = (idx & 31) * 4;     // 0..124
        float4 v = make_float4(0.f, 0.f, 0.f, 0.f);
        int gr = row0 + m;
        if (gr < M) v = *reinterpret_cast<const float4*>(A + (size_t)gr * 128 + k);
        As[m * 129 + k + 0] = v.x;
        As[m * 129 + k + 1] = v.y;
        As[m * 129 + k + 2] = v.z;
        As[m * 129 + k + 3] = v.w;
    }
    // Load B tile (all K rows, cols col0..col0+127). N is a multiple of 4 -> aligned float4.
    #pragma unroll
    for (int i = 0; i < 16; i++) {
        int idx = t + i * 256;
        int k   = idx >> 5;
        int c   = (idx & 31) * 4;
        int gc  = col0 + c;
        float4 v = make_float4(0.f, 0.f, 0.f, 0.f);
        if (gc + 3 < N) v = *reinterpret_cast<const float4*>(B + (size_t)k * N + gc);
        *reinterpret_cast<float4*>(Bs + k * 128 + c) = v;
    }
    __syncthreads();

    const int tx = t & 15, ty = t >> 4;
    const int mr = ty * 8, nr = tx * 8;

    float acc[8][8];
    #pragma unroll
    for (int i = 0; i < 8; i++)
        #pragma unroll
        for (int j = 0; j < 8; j++) acc[i][j] = 0.f;

    #pragma unroll 4
    for (int k = 0; k < 128; k++) {
        float a[8], b[8];
        #pragma unroll
        for (int i = 0; i < 8; i++) a[i] = As[(mr + i) * 129 + k];
        *reinterpret_cast<float4*>(b)     = *reinterpret_cast<const float4*>(Bs + k * 128 + nr);
        *reinterpret_cast<float4*>(b + 4) = *reinterpret_cast<const float4*>(Bs + k * 128 + nr + 4);
        #pragma unroll
        for (int i = 0; i < 8; i++)
            #pragma unroll
            for (int j = 0; j < 8; j++)
                acc[i][j] += a[i] * b[j];
    }

    const bool full_cols = (col0 + 127 < N);
    #pragma unroll
    for (int i = 0; i < 8; i++) {
        int gr = row0 + mr + i;
        if (gr >= M) continue;
        float* crow = C + (size_t)gr * N;
        if (full_cols) {
            #pragma unroll
            for (int j = 0; j < 8; j += 4) {
                int gc = col0 + nr + j;
                float4 v = make_float4(acc[i][j], acc[i][j + 1], acc[i][j + 2], acc[i][j + 3]);
                if (bias) {
                    v.x += __ldg(bias + gc + 0);
                    v.y += __ldg(bias + gc + 1);
                    v.z += __ldg(bias + gc + 2);
                    v.w += __ldg(bias + gc + 3);
                }
                *reinterpret_cast<float4*>(crow + gc) = v;
            }
        } else {
            #pragma unroll
            for (int j = 0; j < 8; j++) {
                int gc = col0 + nr + j;
                if (gc < N) {
                    float v = acc[i][j];
                    if (bias) v += __ldg(bias + gc);
                    crow[gc] = v;
                }
            }
        }
    }
}

// ---------------- launch ----------------
extern "C" void kernel_launch(void* const* d_in, const int* in_sizes, int n_in,
                              void* d_out, int out_size) {
    const void*  ei  = d_in[0];                 // edge_index [2,E] (int64 or int32 — sniffed)
    const float* ew  = (const float*)d_in[1];   // edge_weight [E]
    const float* emb = (const float*)d_in[2];   // [N,128]
    const float* W1  = (const float*)d_in[3];
    const float* b1  = (const float*)d_in[4];
    const float* W2  = (const float*)d_in[5];
    const float* b2  = (const float*)d_in[6];
    const float* Wp  = (const float*)d_in[7];   // [128,1000]
    const float* bp  = (const float*)d_in[8];
    float* out = (float*)d_out;

    float *bufA, *bufB, *deg, *nrm;
    cudaGetSymbolAddress((void**)&bufA, g_bufA);
    cudaGetSymbolAddress((void**)&bufB, g_bufB);
    cudaGetSymbolAddress((void**)&deg,  g_deg);
    cudaGetSymbolAddress((void**)&nrm,  g_norm);

    cudaFuncSetAttribute(gemm_k128, cudaFuncAttributeMaxDynamicSharedMemorySize, GEMM_SMEM);

    // 0. dtype sniff + normalization prep
    sniff_dtype_kernel<<<1, 32>>>((const int*)ei);
    zero_deg_kernel<<<(NN + 255) / 256, 256>>>(deg);
    deg_kernel<<<(NE + 255) / 256, 256>>>(ei, ew, deg);
    dinv_kernel<<<(NN + 255) / 256, 256>>>(deg);
    norm_kernel<<<(NE + 255) / 256, 256>>>(ei, ew, deg, nrm);

    dim3 gT((NN + 127) / 128, 1);      // N=128 transforms
    dim3 gP((NN + 127) / 128, (NU + 127) / 128);

    // Layer 1: h = emb @ W1 ; h1 = scatter(norm * h) + b1
    gemm_k128<<<gT, 256, GEMM_SMEM>>>(emb, W1, nullptr, bufA, NN, HH);
    init_bias_kernel<<<(NN * HH + 255) / 256, 256>>>(bufB, b1);
    scatter_kernel<<<(NE * 32) / 256, 256>>>(ei, nrm, bufA, bufB);

    // Layer 2: h = h1 @ W2 ; h2 = scatter(norm * h) + b2  (reuse buffers)
    gemm_k128<<<gT, 256, GEMM_SMEM>>>(bufB, W2, nullptr, bufA, NN, HH);
    init_bias_kernel<<<(NN * HH + 255) / 256, 256>>>(bufB, b2);
    scatter_kernel<<<(NE * 32) / 256, 256>>>(ei, nrm, bufA, bufB);

    // Projection: out = h2 @ Wp + bp
    gemm_k128<<<gP, 256, GEMM_SMEM>>>(bufB, Wp, bp, out, NN, NU);
}

// round 3
// speedup vs baseline: 1.1137x; 1.1137x over previous
#include <cuda_runtime.h>
#include <cuda_bf16.h>
#include <cstdint>

#define NN 100000
#define NE 640000
#define HH 128
#define NU 1000
#define MTILES 782   // ceil(100000/128)

// ---------------- scratch (static device memory; no runtime allocs) ----------------
__device__ float g_bufA[(size_t)NN * HH];   // 51.2 MB
__device__ float g_bufB[(size_t)NN * HH];   // 51.2 MB
__device__ float g_deg[NN];
__device__ float g_norm[NE];
__device__ int   g_is64;

__device__ __nv_bfloat16 g_Ahi[(size_t)NN * HH];   // 25.6 MB
__device__ __nv_bfloat16 g_Alo[(size_t)NN * HH];   // 25.6 MB
__device__ __nv_bfloat16 g_Wpthi[1024 * 128];      // Wp^T hi, padded N->1024
__device__ __nv_bfloat16 g_Wptlo[1024 * 128];
__device__ __nv_bfloat16 g_W1thi[128 * 128];
__device__ __nv_bfloat16 g_W1tlo[128 * 128];
__device__ __nv_bfloat16 g_W2thi[128 * 128];
__device__ __nv_bfloat16 g_W2tlo[128 * 128];

// ---------------- dtype sniffing ----------------
__global__ void sniff_dtype_kernel(const int* __restrict__ ei32) {
    if (threadIdx.x == 0 && blockIdx.x == 0) {
        int all_zero = 1;
        for (int i = 0; i < 256; i++) {
            if (ei32[2 * i + 1] != 0) { all_zero = 0; break; }
        }
        g_is64 = all_zero;
    }
}

__device__ __forceinline__ int edge_idx(const void* ei, int pos) {
    if (g_is64) return (int)((const long long*)ei)[pos];
    return ((const int*)ei)[pos];
}

// ---------------- small prep kernels ----------------
__global__ void zero_deg_kernel(float* deg) {
    int i = blockIdx.x * blockDim.x + threadIdx.x;
    if (i < NN) deg[i] = 0.f;
}

__global__ void deg_kernel(const void* __restrict__ ei, const float* __restrict__ w, float* deg) {
    int e = blockIdx.x * blockDim.x + threadIdx.x;
    if (e < NE) {
        int c = edge_idx(ei, NE + e);
        atomicAdd(deg + c, w[e]);
    }
}

__global__ void dinv_kernel(float* deg) {
    int i = blockIdx.x * blockDim.x + threadIdx.x;
    if (i < NN) {
        float d = deg[i];
        deg[i] = (d > 0.f) ? rsqrtf(fmaxf(d, 1e-30f)) : 0.f;
    }
}

__global__ void norm_kernel(const void* __restrict__ ei, const float* __restrict__ w,
                            const float* __restrict__ dinv, float* __restrict__ nrm) {
    int e = blockIdx.x * blockDim.x + threadIdx.x;
    if (e < NE) {
        int r = edge_idx(ei, e);
        int c = edge_idx(ei, NE + e);
        nrm[e] = dinv[r] * w[e] * dinv[c];
    }
}

__global__ void init_bias_kernel(float* __restrict__ buf, const float* __restrict__ bias) {
    int i = blockIdx.x * blockDim.x + threadIdx.x;
    if (i < NN * HH) buf[i] = bias[i & (HH - 1)];
}

// ---------------- edge scatter: agg[col] += norm * h[row] ----------------
__global__ void scatter_kernel(const void* __restrict__ ei, const float* __restrict__ nrm,
                               const float* __restrict__ h, float* __restrict__ agg) {
    int idx = blockIdx.x * blockDim.x + threadIdx.x;
    int e = idx >> 5;
    if (e >= NE) return;
    int lane = idx & 31;
    int r = edge_idx(ei, e);
    int c = edge_idx(ei, NE + e);
    float nw = __ldg(nrm + e);
    float4 v = *reinterpret_cast<const float4*>(h + (size_t)r * HH + lane * 4);
    v.x *= nw; v.y *= nw; v.z *= nw; v.w *= nw;
    float* dst = agg + (size_t)c * HH + lane * 4;
    asm volatile("red.global.add.v4.f32 [%0], {%1,%2,%3,%4};"
                 :: "l"(dst), "f"(v.x), "f"(v.y), "f"(v.z), "f"(v.w)
                 : "memory");
}

// ---------------- split pre-passes ----------------
__global__ void split_a_kernel(const float* __restrict__ x,
                               __nv_bfloat16* __restrict__ hi, __nv_bfloat16* __restrict__ lo) {
    int i = blockIdx.x * blockDim.x + threadIdx.x;
    if (i < NN * HH) {
        float v = x[i];
        __nv_bfloat16 h = __float2bfloat16(v);
        float r = v - __bfloat162float(h);
        hi[i] = h;
        lo[i] = __float2bfloat16(r);
    }
}

// transpose + split W[128,N] -> Wt[Npad,128] bf16 hi/lo (zero-padded rows)
__global__ void split_w_kernel(const float* __restrict__ W,
                               __nv_bfloat16* __restrict__ bhi, __nv_bfloat16* __restrict__ blo,
                               int N, int Npad) {
    int i = blockIdx.x * blockDim.x + threadIdx.x;
    if (i < Npad * 128) {
        int n = i >> 7, k = i & 127;
        float v = (n < N) ? W[k * N + n] : 0.f;
        __nv_bfloat16 h = __float2bfloat16(v);
        float r = v - __bfloat162float(h);
        bhi[i] = h;
        blo[i] = __float2bfloat16(r);
    }
}

// =====================================================================================
//  Split-bf16 mma.sync GEMM: C[100000, Nvalid] = A[100000,128] @ Bt^T (+bias)
//  Bt is [Npad,128] (n-major, k contiguous). 3 passes: Ahi*Bhi + Ahi*Blo + Alo*Bhi.
// =====================================================================================

__device__ __forceinline__ uint32_t smem_u32(const void* p) {
    uint32_t a;
    asm("{ .reg .u64 t; cvta.to.shared.u64 t, %1; cvt.u32.u64 %0, t; }" : "=r"(a) : "l"(p));
    return a;
}

#define LDSM4(r0, r1, r2, r3, addr)                                              \
    asm volatile("ldmatrix.sync.aligned.m8n8.x4.shared.b16 {%0,%1,%2,%3}, [%4];" \
                 : "=r"(r0), "=r"(r1), "=r"(r2), "=r"(r3) : "r"(addr))

#define MMA16816(c0, c1, c2, c3, a0, a1, a2, a3, b0, b1)                      \
    asm volatile("mma.sync.aligned.m16n8k16.row.col.f32.bf16.bf16.f32 "       \
                 "{%0,%1,%2,%3},{%4,%5,%6,%7},{%8,%9},{%0,%1,%2,%3};"         \
                 : "+f"(c0), "+f"(c1), "+f"(c2), "+f"(c3)                     \
                 : "r"(a0), "r"(a1), "r"(a2), "r"(a3), "r"(b0), "r"(b1))

// padded smem tiles: 128 rows x 136 bf16 (272 B row stride -> conflict-free ldsm)
#define TILE_B 34816u            // 128 * 272
#define S_AH   0u
#define S_AL   34816u
#define S_BH   69632u
#define S_BL   104448u
#define GEMM_MMA_SMEM 139264

__global__ void __launch_bounds__(256, 1)
gemm_mma_split(const __nv_bfloat16* __restrict__ Ahi, const __nv_bfloat16* __restrict__ Alo,
               const __nv_bfloat16* __restrict__ Bhi, const __nv_bfloat16* __restrict__ Blo,
               const float* __restrict__ bias, float* __restrict__ C,
               int Nvalid, int ldc) {
    extern __shared__ char smc[];
    const uint32_t sb = smem_u32(smc);

    const int tid  = threadIdx.x;
    const int lane = tid & 31;
    const int wid  = tid >> 5;
    const int wm   = wid & 3;    // 4 warps over M (32 rows each)
    const int wn   = wid >> 2;   // 2 warps over N (64 cols each)
    const int nt   = blockIdx.x;
    const int mt   = blockIdx.y;
    const int m0   = mt * 128;

    // ---- load A tile (hi+lo), zero OOB rows ----
    for (int idx = tid; idx < 2048; idx += 256) {
        int r = idx >> 4, c = idx & 15;
        int row = m0 + r;
        uint4 vh = make_uint4(0, 0, 0, 0), vl = make_uint4(0, 0, 0, 0);
        if (row < NN) {
            vh = *reinterpret_cast<const uint4*>(Ahi + (size_t)row * 128 + c * 8);
            vl = *reinterpret_cast<const uint4*>(Alo + (size_t)row * 128 + c * 8);
        }
        uint32_t o = (uint32_t)r * 272u + (uint32_t)c * 16u;
        *reinterpret_cast<uint4*>(smc + S_AH + o) = vh;
        *reinterpret_cast<uint4*>(smc + S_AL + o) = vl;
    }
    // ---- load B tile (hi+lo); Bt rows are padded so always in-bounds ----
    for (int idx = tid; idx < 2048; idx += 256) {
        int r = idx >> 4, c = idx & 15;
        int n = nt * 128 + r;
        uint4 vh = *reinterpret_cast<const uint4*>(Bhi + (size_t)n * 128 + c * 8);
        uint4 vl = *reinterpret_cast<const uint4*>(Blo + (size_t)n * 128 + c * 8);
        uint32_t o = (uint32_t)r * 272u + (uint32_t)c * 16u;
        *reinterpret_cast<uint4*>(smc + S_BH + o) = vh;
        *reinterpret_cast<uint4*>(smc + S_BL + o) = vl;
    }
    __syncthreads();

    // ldmatrix per-lane address offsets (within tile):
    // lanes 0-7: rows+0 @k0 | 8-15: rows+8 @k0 | 16-23: rows+0 @k8 | 24-31: rows+8 @k8
    const uint32_t lrow = (uint32_t)((lane & 7) + ((lane >> 3) & 1) * 8);
    const uint32_t lkh  = (uint32_t)(lane >> 4) * 16u;   // k-half byte offset
    const uint32_t aoff = ((uint32_t)(wm * 32) + lrow) * 272u + lkh;
    const uint32_t boff = ((uint32_t)(wn * 64) + lrow) * 272u + lkh;

    float acc[2][8][4];
    #pragma unroll
    for (int i = 0; i < 2; i++)
        #pragma unroll
        for (int j = 0; j < 8; j++)
            #pragma unroll
            for (int q = 0; q < 4; q++) acc[i][j][q] = 0.f;

    #pragma unroll
    for (int p = 0; p < 3; p++) {
        const uint32_t abase = sb + (p == 2 ? S_AL : S_AH) + aoff;
        const uint32_t bbase = sb + (p == 1 ? S_BL : S_BH) + boff;
        #pragma unroll
        for (int ks = 0; ks < 8; ks++) {
            const uint32_t ko = (uint32_t)ks * 32u;
            uint32_t a[2][4];
            LDSM4(a[0][0], a[0][1], a[0][2], a[0][3], abase + ko);
            LDSM4(a[1][0], a[1][1], a[1][2], a[1][3], abase + ko + 16u * 272u);
            uint32_t b[4][4];
            #pragma unroll
            for (int jj = 0; jj < 4; jj++)
                LDSM4(b[jj][0], b[jj][1], b[jj][2], b[jj][3],
                      bbase + ko + (uint32_t)jj * 16u * 272u);
            #pragma unroll
            for (int i = 0; i < 2; i++) {
                #pragma unroll
                for (int jj = 0; jj < 4; jj++) {
                    MMA16816(acc[i][jj * 2][0], acc[i][jj * 2][1], acc[i][jj * 2][2], acc[i][jj * 2][3],
                             a[i][0], a[i][1], a[i][2], a[i][3], b[jj][0], b[jj][2]);
                    MMA16816(acc[i][jj * 2 + 1][0], acc[i][jj * 2 + 1][1], acc[i][jj * 2 + 1][2], acc[i][jj * 2 + 1][3],
                             a[i][0], a[i][1], a[i][2], a[i][3], b[jj][1], b[jj][3]);
                }
            }
        }
    }

    // ---- epilogue: fragment (r = lane>>2, c2 = (lane&3)*2); rows r and r+8 ----
    const int rbase = m0 + wm * 32 + (lane >> 2);
    const int cbase = nt * 128 + wn * 64 + (lane & 3) * 2;
    #pragma unroll
    for (int i = 0; i < 2; i++) {
        const int r0 = rbase + i * 16;
        const int r1 = r0 + 8;
        #pragma unroll
        for (int j = 0; j < 8; j++) {
            const int col = cbase + j * 8;
            if (col >= Nvalid) continue;
            float bx = 0.f, by = 0.f;
            if (bias) { bx = __ldg(bias + col); by = __ldg(bias + col + 1); }
            if (r0 < NN) {
                float2 v = make_float2(acc[i][j][0] + bx, acc[i][j][1] + by);
                *reinterpret_cast<float2*>(C + (size_t)r0 * ldc + col) = v;
            }
            if (r1 < NN) {
                float2 v = make_float2(acc[i][j][2] + bx, acc[i][j][3] + by);
                *reinterpret_cast<float2*>(C + (size_t)r1 * ldc + col) = v;
            }
        }
    }
}

// ---------------- launch ----------------
extern "C" void kernel_launch(void* const* d_in, const int* in_sizes, int n_in,
                              void* d_out, int out_size) {
    const void*  ei  = d_in[0];
    const float* ew  = (const float*)d_in[1];
    const float* emb = (const float*)d_in[2];
    const float* W1  = (const float*)d_in[3];
    const float* b1  = (const float*)d_in[4];
    const float* W2  = (const float*)d_in[5];
    const float* b2  = (const float*)d_in[6];
    const float* Wp  = (const float*)d_in[7];
    const float* bp  = (const float*)d_in[8];
    float* out = (float*)d_out;

    float *bufA, *bufB, *deg, *nrm;
    __nv_bfloat16 *ahi, *alo, *wpthi, *wptlo, *w1thi, *w1tlo, *w2thi, *w2tlo;
    cudaGetSymbolAddress((void**)&bufA,  g_bufA);
    cudaGetSymbolAddress((void**)&bufB,  g_bufB);
    cudaGetSymbolAddress((void**)&deg,   g_deg);
    cudaGetSymbolAddress((void**)&nrm,   g_norm);
    cudaGetSymbolAddress((void**)&ahi,   g_Ahi);
    cudaGetSymbolAddress((void**)&alo,   g_Alo);
    cudaGetSymbolAddress((void**)&wpthi, g_Wpthi);
    cudaGetSymbolAddress((void**)&wptlo, g_Wptlo);
    cudaGetSymbolAddress((void**)&w1thi, g_W1thi);
    cudaGetSymbolAddress((void**)&w1tlo, g_W1tlo);
    cudaGetSymbolAddress((void**)&w2thi, g_W2thi);
    cudaGetSymbolAddress((void**)&w2tlo, g_W2tlo);

    cudaFuncSetAttribute(gemm_mma_split, cudaFuncAttributeMaxDynamicSharedMemorySize,
                         GEMM_MMA_SMEM);

    // prep
    sniff_dtype_kernel<<<1, 32>>>((const int*)ei);
    zero_deg_kernel<<<(NN + 255) / 256, 256>>>(deg);
    deg_kernel<<<(NE + 255) / 256, 256>>>(ei, ew, deg);
    dinv_kernel<<<(NN + 255) / 256, 256>>>(deg);
    norm_kernel<<<(NE + 255) / 256, 256>>>(ei, ew, deg, nrm);
    split_w_kernel<<<(128 * 128 + 255) / 256, 256>>>(W1, w1thi, w1tlo, 128, 128);
    split_w_kernel<<<(128 * 128 + 255) / 256, 256>>>(W2, w2thi, w2tlo, 128, 128);
    split_w_kernel<<<(1024 * 128 + 255) / 256, 256>>>(Wp, wpthi, wptlo, NU, 1024);

    // Layer 1: h = emb @ W1 ; h1 = scatter(norm * h) + b1
    split_a_kernel<<<(NN * HH + 255) / 256, 256>>>(emb, ahi, alo);
    gemm_mma_split<<<dim3(1, MTILES), 256, GEMM_MMA_SMEM>>>(
        ahi, alo, w1thi, w1tlo, nullptr, bufA, HH, HH);
    init_bias_kernel<<<(NN * HH + 255) / 256, 256>>>(bufB, b1);
    scatter_kernel<<<(NE * 32) / 256, 256>>>(ei, nrm, bufA, bufB);

    // Layer 2: h = h1 @ W2 ; h2 = scatter(norm * h) + b2
    split_a_kernel<<<(NN * HH + 255) / 256, 256>>>(bufB, ahi, alo);
    gemm_mma_split<<<dim3(1, MTILES), 256, GEMM_MMA_SMEM>>>(
        ahi, alo, w2thi, w2tlo, nullptr, bufA, HH, HH);
    init_bias_kernel<<<(NN * HH + 255) / 256, 256>>>(bufB, b2);
    scatter_kernel<<<(NE * 32) / 256, 256>>>(ei, nrm, bufA, bufB);

    // Projection: out = h2 @ Wp + bp
    split_a_kernel<<<(NN * HH + 255) / 256, 256>>>(bufB, ahi, alo);
    gemm_mma_split<<<dim3(8, MTILES), 256, GEMM_MMA_SMEM>>>(
        ahi, alo, wpthi, wptlo, bp, out, NU, NU);
}

// round 4
// speedup vs baseline: 1.5087x; 1.3547x over previous
#include <cuda_runtime.h>
#include <cuda_bf16.h>
#include <cstdint>

#define NN 100000
#define NE 640000
#define HH 128
#define NU 1000
#define MTILES 782   // ceil(100000/128)

// ---------------- scratch (static device memory; no runtime allocs) ----------------
__device__ float g_bufA[(size_t)NN * HH];   // 51.2 MB
__device__ float g_bufB[(size_t)NN * HH];   // 51.2 MB
__device__ float g_deg[NN];
__device__ float g_norm[NE];
__device__ int   g_is64;

__device__ __nv_bfloat16 g_Wpthi[1024 * 128];      // Wp^T hi, padded N->1024
__device__ __nv_bfloat16 g_Wptlo[1024 * 128];
__device__ __nv_bfloat16 g_W1thi[128 * 128];
__device__ __nv_bfloat16 g_W1tlo[128 * 128];
__device__ __nv_bfloat16 g_W2thi[128 * 128];
__device__ __nv_bfloat16 g_W2tlo[128 * 128];

// ---------------- dtype sniffing ----------------
__global__ void sniff_dtype_kernel(const int* __restrict__ ei32) {
    if (threadIdx.x == 0 && blockIdx.x == 0) {
        int all_zero = 1;
        for (int i = 0; i < 256; i++) {
            if (ei32[2 * i + 1] != 0) { all_zero = 0; break; }
        }
        g_is64 = all_zero;
    }
}

__device__ __forceinline__ int edge_idx(const void* ei, int pos) {
    if (g_is64) return (int)((const long long*)ei)[pos];
    return ((const int*)ei)[pos];
}

// ---------------- small prep kernels ----------------
__global__ void zero_deg_kernel(float* deg) {
    int i = blockIdx.x * blockDim.x + threadIdx.x;
    if (i < NN) deg[i] = 0.f;
}

__global__ void deg_kernel(const void* __restrict__ ei, const float* __restrict__ w, float* deg) {
    int e = blockIdx.x * blockDim.x + threadIdx.x;
    if (e < NE) {
        int c = edge_idx(ei, NE + e);
        atomicAdd(deg + c, w[e]);
    }
}

__global__ void dinv_kernel(float* deg) {
    int i = blockIdx.x * blockDim.x + threadIdx.x;
    if (i < NN) {
        float d = deg[i];
        deg[i] = (d > 0.f) ? rsqrtf(fmaxf(d, 1e-30f)) : 0.f;
    }
}

__global__ void norm_kernel(const void* __restrict__ ei, const float* __restrict__ w,
                            const float* __restrict__ dinv, float* __restrict__ nrm) {
    int e = blockIdx.x * blockDim.x + threadIdx.x;
    if (e < NE) {
        int r = edge_idx(ei, e);
        int c = edge_idx(ei, NE + e);
        nrm[e] = dinv[r] * w[e] * dinv[c];
    }
}

__global__ void init_bias_kernel(float* __restrict__ buf, const float* __restrict__ bias) {
    int i = blockIdx.x * blockDim.x + threadIdx.x;
    if (i < NN * HH) buf[i] = bias[i & (HH - 1)];
}

// ---------------- edge scatter: agg[col] += norm * h[row] ----------------
__global__ void scatter_kernel(const void* __restrict__ ei, const float* __restrict__ nrm,
                               const float* __restrict__ h, float* __restrict__ agg) {
    int idx = blockIdx.x * blockDim.x + threadIdx.x;
    int e = idx >> 5;
    if (e >= NE) return;
    int lane = idx & 31;
    int r = edge_idx(ei, e);
    int c = edge_idx(ei, NE + e);
    float nw = __ldg(nrm + e);
    float4 v = *reinterpret_cast<const float4*>(h + (size_t)r * HH + lane * 4);
    v.x *= nw; v.y *= nw; v.z *= nw; v.w *= nw;
    float* dst = agg + (size_t)c * HH + lane * 4;
    asm volatile("red.global.add.v4.f32 [%0], {%1,%2,%3,%4};"
                 :: "l"(dst), "f"(v.x), "f"(v.y), "f"(v.z), "f"(v.w)
                 : "memory");
}

// ---------------- weight split pre-pass: W[128,N] -> Wt[Npad,128] bf16 hi/lo ----------------
__global__ void split_w_kernel(const float* __restrict__ W,
                               __nv_bfloat16* __restrict__ bhi, __nv_bfloat16* __restrict__ blo,
                               int N, int Npad) {
    int i = blockIdx.x * blockDim.x + threadIdx.x;
    if (i < Npad * 128) {
        int n = i >> 7, k = i & 127;
        float v = (n < N) ? W[k * N + n] : 0.f;
        __nv_bfloat16 h = __float2bfloat16(v);
        float r = v - __bfloat162float(h);
        bhi[i] = h;
        blo[i] = __float2bfloat16(r);
    }
}

// =====================================================================================
//  Split-bf16 mma.sync GEMM: C[100000, Nvalid] = A_f32[100000,128] @ Bt^T (+bias)
//  A is fp32 in global; split to bf16 hi/lo in the staging path.
//  Bt is [Npad,128] bf16 hi/lo (n-major). 3 passes: Ahi*Bhi + Ahi*Blo + Alo*Bhi.
//  CTA tile 128M x 64N, 102 KB smem, 2 CTAs/SM.
// =====================================================================================

__device__ __forceinline__ uint32_t smem_u32(const void* p) {
    uint32_t a;
    asm("{ .reg .u64 t; cvta.to.shared.u64 t, %1; cvt.u32.u64 %0, t; }" : "=r"(a) : "l"(p));
    return a;
}

#define LDSM4(r0, r1, r2, r3, addr)                                              \
    asm volatile("ldmatrix.sync.aligned.m8n8.x4.shared.b16 {%0,%1,%2,%3}, [%4];" \
                 : "=r"(r0), "=r"(r1), "=r"(r2), "=r"(r3) : "r"(addr))

#define MMA16816(c0, c1, c2, c3, a0, a1, a2, a3, b0, b1)                      \
    asm volatile("mma.sync.aligned.m16n8k16.row.col.f32.bf16.bf16.f32 "       \
                 "{%0,%1,%2,%3},{%4,%5,%6,%7},{%8,%9},{%0,%1,%2,%3};"         \
                 : "+f"(c0), "+f"(c1), "+f"(c2), "+f"(c3)                     \
                 : "r"(a0), "r"(a1), "r"(a2), "r"(a3), "r"(b0), "r"(b1))

// padded smem tiles: rows x 136 bf16 (272 B row stride -> conflict-free ldsm)
#define S_AH   0u
#define S_AL   34816u       // 128*272
#define S_BH   69632u
#define S_BL   87040u       // + 64*272
#define GEMM_MMA_SMEM 104448

__global__ void __launch_bounds__(256, 2)
gemm_mma_split(const float* __restrict__ A,
               const __nv_bfloat16* __restrict__ Bhi, const __nv_bfloat16* __restrict__ Blo,
               const float* __restrict__ bias, float* __restrict__ C,
               int Nvalid, int ldc) {
    extern __shared__ char smc[];
    const uint32_t sb = smem_u32(smc);

    const int tid  = threadIdx.x;
    const int lane = tid & 31;
    const int wid  = tid >> 5;
    const int wm   = wid & 3;    // 4 warps over M (32 rows each)
    const int wn   = wid >> 2;   // 2 warps over N (32 cols each)
    const int nt   = blockIdx.x;
    const int mt   = blockIdx.y;
    const int m0   = mt * 128;

    // ---- stage A tile: load fp32, split to bf16 hi/lo in registers ----
    #pragma unroll
    for (int it = 0; it < 16; it++) {
        int idx = tid + it * 256;        // 0..4095 float4 chunks
        int r = idx >> 5, c = idx & 31;  // 32 chunks of 4 floats per row
        int row = m0 + r;
        float4 v = make_float4(0.f, 0.f, 0.f, 0.f);
        if (row < NN) v = *reinterpret_cast<const float4*>(A + (size_t)row * 128 + c * 4);
        __nv_bfloat16 h0 = __float2bfloat16(v.x);
        __nv_bfloat16 h1 = __float2bfloat16(v.y);
        __nv_bfloat16 h2 = __float2bfloat16(v.z);
        __nv_bfloat16 h3 = __float2bfloat16(v.w);
        __nv_bfloat162 hi01 = __nv_bfloat162(h0, h1);
        __nv_bfloat162 hi23 = __nv_bfloat162(h2, h3);
        __nv_bfloat162 lo01 = __nv_bfloat162(__float2bfloat16(v.x - __bfloat162float(h0)),
                                             __float2bfloat16(v.y - __bfloat162float(h1)));
        __nv_bfloat162 lo23 = __nv_bfloat162(__float2bfloat16(v.z - __bfloat162float(h2)),
                                             __float2bfloat16(v.w - __bfloat162float(h3)));
        uint32_t o = (uint32_t)r * 272u + (uint32_t)c * 8u;
        *reinterpret_cast<uint2*>(smc + S_AH + o) =
            make_uint2(*(uint32_t*)&hi01, *(uint32_t*)&hi23);
        *reinterpret_cast<uint2*>(smc + S_AL + o) =
            make_uint2(*(uint32_t*)&lo01, *(uint32_t*)&lo23);
    }
    // ---- stage B tile (hi+lo), 64 n-rows; Bt is padded so always in-bounds ----
    #pragma unroll
    for (int it = 0; it < 4; it++) {
        int idx = tid + it * 256;        // 0..1023
        int r = idx >> 4, c = idx & 15;
        int n = nt * 64 + r;
        uint4 vh = *reinterpret_cast<const uint4*>(Bhi + (size_t)n * 128 + c * 8);
        uint4 vl = *reinterpret_cast<const uint4*>(Blo + (size_t)n * 128 + c * 8);
        uint32_t o = (uint32_t)r * 272u + (uint32_t)c * 16u;
        *reinterpret_cast<uint4*>(smc + S_BH + o) = vh;
        *reinterpret_cast<uint4*>(smc + S_BL + o) = vl;
    }
    __syncthreads();

    // ldmatrix per-lane offsets: lanes 0-15 pick 16 rows, lanes 16-31 the k+8 half
    const uint32_t lrow = (uint32_t)(lane & 15);
    const uint32_t lkh  = (uint32_t)(lane >> 4) * 16u;
    const uint32_t aoff = ((uint32_t)(wm * 32) + lrow) * 272u + lkh;
    const uint32_t boff = ((uint32_t)(wn * 32) + lrow) * 272u + lkh;

    float acc[2][4][4];
    #pragma unroll
    for (int i = 0; i < 2; i++)
        #pragma unroll
        for (int j = 0; j < 4; j++)
            #pragma unroll
            for (int q = 0; q < 4; q++) acc[i][j][q] = 0.f;

    #pragma unroll
    for (int p = 0; p < 3; p++) {
        const uint32_t abase = sb + (p == 2 ? S_AL : S_AH) + aoff;
        const uint32_t bbase = sb + (p == 1 ? S_BL : S_BH) + boff;
        #pragma unroll
        for (int ks = 0; ks < 8; ks++) {
            const uint32_t ko = (uint32_t)ks * 32u;
            uint32_t a[2][4];
            LDSM4(a[0][0], a[0][1], a[0][2], a[0][3], abase + ko);
            LDSM4(a[1][0], a[1][1], a[1][2], a[1][3], abase + ko + 16u * 272u);
            uint32_t b[2][4];
            LDSM4(b[0][0], b[0][1], b[0][2], b[0][3], bbase + ko);
            LDSM4(b[1][0], b[1][1], b[1][2], b[1][3], bbase + ko + 16u * 272u);
            #pragma unroll
            for (int i = 0; i < 2; i++) {
                #pragma unroll
                for (int jj = 0; jj < 2; jj++) {
                    MMA16816(acc[i][jj * 2][0], acc[i][jj * 2][1],
                             acc[i][jj * 2][2], acc[i][jj * 2][3],
                             a[i][0], a[i][1], a[i][2], a[i][3], b[jj][0], b[jj][2]);
                    MMA16816(acc[i][jj * 2 + 1][0], acc[i][jj * 2 + 1][1],
                             acc[i][jj * 2 + 1][2], acc[i][jj * 2 + 1][3],
                             a[i][0], a[i][1], a[i][2], a[i][3], b[jj][1], b[jj][3]);
                }
            }
        }
    }

    // ---- epilogue ----
    const int rbase = m0 + wm * 32 + (lane >> 2);
    const int cbase = nt * 64 + wn * 32 + (lane & 3) * 2;
    #pragma unroll
    for (int i = 0; i < 2; i++) {
        const int r0 = rbase + i * 16;
        const int r1 = r0 + 8;
        #pragma unroll
        for (int j = 0; j < 4; j++) {
            const int col = cbase + j * 8;
            if (col >= Nvalid) continue;
            float bx = 0.f, by = 0.f;
            if (bias) { bx = __ldg(bias + col); by = __ldg(bias + col + 1); }
            if (r0 < NN) {
                float2 v = make_float2(acc[i][j][0] + bx, acc[i][j][1] + by);
                *reinterpret_cast<float2*>(C + (size_t)r0 * ldc + col) = v;
            }
            if (r1 < NN) {
                float2 v = make_float2(acc[i][j][2] + bx, acc[i][j][3] + by);
                *reinterpret_cast<float2*>(C + (size_t)r1 * ldc + col) = v;
            }
        }
    }
}

// ---------------- launch ----------------
extern "C" void kernel_launch(void* const* d_in, const int* in_sizes, int n_in,
                              void* d_out, int out_size) {
    const void*  ei  = d_in[0];
    const float* ew  = (const float*)d_in[1];
    const float* emb = (const float*)d_in[2];
    const float* W1  = (const float*)d_in[3];
    const float* b1  = (const float*)d_in[4];
    const float* W2  = (const float*)d_in[5];
    const float* b2  = (const float*)d_in[6];
    const float* Wp  = (const float*)d_in[7];
    const float* bp  = (const float*)d_in[8];
    float* out = (float*)d_out;

    float *bufA, *bufB, *deg, *nrm;
    __nv_bfloat16 *wpthi, *wptlo, *w1thi, *w1tlo, *w2thi, *w2tlo;
    cudaGetSymbolAddress((void**)&bufA,  g_bufA);
    cudaGetSymbolAddress((void**)&bufB,  g_bufB);
    cudaGetSymbolAddress((void**)&deg,   g_deg);
    cudaGetSymbolAddress((void**)&nrm,   g_norm);
    cudaGetSymbolAddress((void**)&wpthi, g_Wpthi);
    cudaGetSymbolAddress((void**)&wptlo, g_Wptlo);
    cudaGetSymbolAddress((void**)&w1thi, g_W1thi);
    cudaGetSymbolAddress((void**)&w1tlo, g_W1tlo);
    cudaGetSymbolAddress((void**)&w2thi, g_W2thi);
    cudaGetSymbolAddress((void**)&w2tlo, g_W2tlo);

    cudaFuncSetAttribute(gemm_mma_split, cudaFuncAttributeMaxDynamicSharedMemorySize,
                         GEMM_MMA_SMEM);

    // prep (ordered so launch #6 is the first MMA GEMM -> ncu -s 5 -c 1 captures it)
    sniff_dtype_kernel<<<1, 32>>>((const int*)ei);                                   // 1
    split_w_kernel<<<(128 * 128 + 255) / 256, 256>>>(W1, w1thi, w1tlo, 128, 128);    // 2
    split_w_kernel<<<(128 * 128 + 255) / 256, 256>>>(W2, w2thi, w2tlo, 128, 128);    // 3
    split_w_kernel<<<(1024 * 128 + 255) / 256, 256>>>(Wp, wpthi, wptlo, NU, 1024);   // 4
    zero_deg_kernel<<<(NN + 255) / 256, 256>>>(deg);                                 // 5

    // Layer 1 transform: h = emb @ W1   (launch #6 - profiled)
    gemm_mma_split<<<dim3(2, MTILES), 256, GEMM_MMA_SMEM>>>(
        emb, w1thi, w1tlo, nullptr, bufA, HH, HH);

    deg_kernel<<<(NE + 255) / 256, 256>>>(ei, ew, deg);
    dinv_kernel<<<(NN + 255) / 256, 256>>>(deg);
    norm_kernel<<<(NE + 255) / 256, 256>>>(ei, ew, deg, nrm);

    // Layer 1 aggregate: h1 = scatter(norm * h) + b1
    init_bias_kernel<<<(NN * HH + 255) / 256, 256>>>(bufB, b1);
    scatter_kernel<<<(NE * 32) / 256, 256>>>(ei, nrm, bufA, bufB);

    // Layer 2: h = h1 @ W2 ; h2 = scatter(norm * h) + b2
    gemm_mma_split<<<dim3(2, MTILES), 256, GEMM_MMA_SMEM>>>(
        bufB, w2thi, w2tlo, nullptr, bufA, HH, HH);
    init_bias_kernel<<<(NN * HH + 255) / 256, 256>>>(bufB, b2);
    scatter_kernel<<<(NE * 32) / 256, 256>>>(ei, nrm, bufA, bufB);

    // Projection: out = h2 @ Wp + bp
    gemm_mma_split<<<dim3(16, MTILES), 256, GEMM_MMA_SMEM>>>(
        bufB, wpthi, wptlo, bp, out, NU, NU);
}

// round 5
// speedup vs baseline: 1.8393x; 1.2191x over previous
#include <cuda_runtime.h>
#include <cuda_bf16.h>
#include <cstdint>

#define NN 100000
#define NE 640000
#define HH 128
#define NU 1000
#define MTILES 782   // ceil(100000/128)

// ---------------- scratch (static device memory; no runtime allocs) ----------------
__device__ float g_bufA[(size_t)NN * HH];   // 51.2 MB  (Z1 = A*X)
__device__ float g_bufB[(size_t)NN * HH];   // 51.2 MB  (Z2 = A*Z1)
__device__ float g_deg[NN];
__device__ float g_v[NN];                   // v = A*1
__device__ float g_norm[NE];
__device__ int   g_is64;

__device__ float g_W2p[128 * NU];           // W2 @ Wp
__device__ float g_Wc[128 * NU];            // W1 @ W2 @ Wp
__device__ float g_c1[NU];                  // b1 @ W2 @ Wp
__device__ float g_c0[NU];                  // b2 @ Wp + bp
__device__ __nv_bfloat16 g_Wcthi[1024 * 128];  // Wc^T hi (padded N->1024)
__device__ __nv_bfloat16 g_Wctlo[1024 * 128];  // Wc^T lo

// ---------------- dtype sniffing ----------------
__global__ void sniff_dtype_kernel(const int* __restrict__ ei32) {
    if (threadIdx.x == 0 && blockIdx.x == 0) {
        int all_zero = 1;
        for (int i = 0; i < 256; i++) {
            if (ei32[2 * i + 1] != 0) { all_zero = 0; break; }
        }
        g_is64 = all_zero;
    }
}

__device__ __forceinline__ int edge_idx(const void* ei, int pos) {
    if (g_is64) return (int)((const long long*)ei)[pos];
    return ((const int*)ei)[pos];
}

// ---------------- fused zero-init: bufA, bufB, deg, v ----------------
#define NZERO (2 * NN * HH + 2 * NN)
__global__ void zero_misc_kernel(float* bufA, float* bufB, float* deg, float* v) {
    int i = blockIdx.x * blockDim.x + threadIdx.x;
    const int n1 = NN * HH;
    if (i < n1)                 bufA[i] = 0.f;
    else if (i < 2 * n1)        bufB[i - 2 * n1 + n1] = 0.f;
    else if (i < 2 * n1 + NN)   deg[i - 2 * n1] = 0.f;
    else if (i < NZERO)         v[i - 2 * n1 - NN] = 0.f;
}

__global__ void deg_kernel(const void* __restrict__ ei, const float* __restrict__ w, float* deg) {
    int e = blockIdx.x * blockDim.x + threadIdx.x;
    if (e < NE) {
        int c = edge_idx(ei, NE + e);
        atomicAdd(deg + c, w[e]);
    }
}

__global__ void dinv_kernel(float* deg) {
    int i = blockIdx.x * blockDim.x + threadIdx.x;
    if (i < NN) {
        float d = deg[i];
        deg[i] = (d > 0.f) ? rsqrtf(fmaxf(d, 1e-30f)) : 0.f;
    }
}

// norm per edge; also accumulates v = A*1 (row sums of normalized adjacency)
__global__ void norm_kernel(const void* __restrict__ ei, const float* __restrict__ w,
                            const float* __restrict__ dinv, float* __restrict__ nrm,
                            float* __restrict__ v) {
    int e = blockIdx.x * blockDim.x + threadIdx.x;
    if (e < NE) {
        int r = edge_idx(ei, e);
        int c = edge_idx(ei, NE + e);
        float val = dinv[r] * w[e] * dinv[c];
        nrm[e] = val;
        atomicAdd(v + c, val);
    }
}

// ---------------- edge scatter: agg[col] += norm * h[row] ----------------
__global__ void scatter_kernel(const void* __restrict__ ei, const float* __restrict__ nrm,
                               const float* __restrict__ h, float* __restrict__ agg) {
    int idx = blockIdx.x * blockDim.x + threadIdx.x;
    int e = idx >> 5;
    if (e >= NE) return;
    int lane = idx & 31;
    int r = edge_idx(ei, e);
    int c = edge_idx(ei, NE + e);
    float nw = __ldg(nrm + e);
    float4 v = *reinterpret_cast<const float4*>(h + (size_t)r * HH + lane * 4);
    v.x *= nw; v.y *= nw; v.z *= nw; v.w *= nw;
    float* dst = agg + (size_t)c * HH + lane * 4;
    asm volatile("red.global.add.v4.f32 [%0], {%1,%2,%3,%4};"
                 :: "l"(dst), "f"(v.x), "f"(v.y), "f"(v.z), "f"(v.w)
                 : "memory");
}

// ---------------- small weight-combine kernels ----------------
// C[128,N] = X[128,128] @ Y[128,N]
__global__ void smallgemm_kernel(const float* __restrict__ X, const float* __restrict__ Y,
                                 float* __restrict__ C, int N) {
    int i = blockIdx.x * blockDim.x + threadIdx.x;
    if (i >= 128 * N) return;
    int m = i / N, n = i % N;
    float s = 0.f;
    #pragma unroll 8
    for (int k = 0; k < 128; k++) s += X[m * 128 + k] * Y[k * N + n];
    C[i] = s;
}

// c1 = b1 @ W2p ; c0 = b2 @ Wp + bp
__global__ void vec_kernel(const float* __restrict__ b1, const float* __restrict__ W2p,
                           const float* __restrict__ b2, const float* __restrict__ Wp,
                           const float* __restrict__ bp,
                           float* __restrict__ c1, float* __restrict__ c0) {
    int n = blockIdx.x * blockDim.x + threadIdx.x;
    if (n >= NU) return;
    float s1 = 0.f, s0 = 0.f;
    #pragma unroll 8
    for (int k = 0; k < 128; k++) {
        s1 += b1[k] * W2p[k * NU + n];
        s0 += b2[k] * Wp[k * NU + n];
    }
    c1[n] = s1;
    c0[n] = s0 + bp[n];
}

// transpose + split W[128,N] -> Wt[Npad,128] bf16 hi/lo (zero-padded rows)
__global__ void split_w_kernel(const float* __restrict__ W,
                               __nv_bfloat16* __restrict__ bhi, __nv_bfloat16* __restrict__ blo,
                               int N, int Npad) {
    int i = blockIdx.x * blockDim.x + threadIdx.x;
    if (i < Npad * 128) {
        int n = i >> 7, k = i & 127;
        float v = (n < N) ? W[k * N + n] : 0.f;
        __nv_bfloat16 h = __float2bfloat16(v);
        float r = v - __bfloat162float(h);
        bhi[i] = h;
        blo[i] = __float2bfloat16(r);
    }
}

// =====================================================================================
//  Split-bf16 mma.sync GEMM + rank-1 epilogue:
//  out[r, n] = (Z2 @ Wc)[r, n] + v[r]*c1[n] + c0[n]
//  A fp32 staged+split to bf16 hi/lo once per CTA; 4 N-tiles (64 cols each) per CTA.
//  3 passes: Ahi*Bhi + Ahi*Blo + Alo*Bhi. 128M x 64N warptiles, 2 CTAs/SM.
// =====================================================================================

__device__ __forceinline__ uint32_t smem_u32(const void* p) {
    uint32_t a;
    asm("{ .reg .u64 t; cvta.to.shared.u64 t, %1; cvt.u32.u64 %0, t; }" : "=r"(a) : "l"(p));
    return a;
}

#define LDSM4(r0, r1, r2, r3, addr)                                              \
    asm volatile("ldmatrix.sync.aligned.m8n8.x4.shared.b16 {%0,%1,%2,%3}, [%4];" \
                 : "=r"(r0), "=r"(r1), "=r"(r2), "=r"(r3) : "r"(addr))

#define MMA16816(c0, c1, c2, c3, a0, a1, a2, a3, b0, b1)                      \
    asm volatile("mma.sync.aligned.m16n8k16.row.col.f32.bf16.bf16.f32 "       \
                 "{%0,%1,%2,%3},{%4,%5,%6,%7},{%8,%9},{%0,%1,%2,%3};"         \
                 : "+f"(c0), "+f"(c1), "+f"(c2), "+f"(c3)                     \
                 : "r"(a0), "r"(a1), "r"(a2), "r"(a3), "r"(b0), "r"(b1))

#define S_AH   0u
#define S_AL   34816u       // 128*272
#define S_BH   69632u
#define S_BL   87040u       // + 64*272
#define GEMM_MMA_SMEM 104448

__global__ void __launch_bounds__(256, 2)
gemm_out(const float* __restrict__ A,
         const __nv_bfloat16* __restrict__ Bhi, const __nv_bfloat16* __restrict__ Blo,
         const float* __restrict__ c0v, const float* __restrict__ c1v,
         const float* __restrict__ vrow, float* __restrict__ C) {
    extern __shared__ char smc[];
    const uint32_t sb = smem_u32(smc);

    const int tid  = threadIdx.x;
    const int lane = tid & 31;
    const int wid  = tid >> 5;
    const int wm   = wid & 3;    // 4 warps over M (32 rows each)
    const int wn   = wid >> 2;   // 2 warps over N (32 cols each)
    const int mt   = blockIdx.y;
    const int m0   = mt * 128;

    // ---- stage A tile once: load fp32, split to bf16 hi/lo in registers ----
    #pragma unroll
    for (int it = 0; it < 16; it++) {
        int idx = tid + it * 256;
        int r = idx >> 5, c = idx & 31;
        int row = m0 + r;
        float4 v = make_float4(0.f, 0.f, 0.f, 0.f);
        if (row < NN) v = *reinterpret_cast<const float4*>(A + (size_t)row * 128 + c * 4);
        __nv_bfloat16 h0 = __float2bfloat16(v.x);
        __nv_bfloat16 h1 = __float2bfloat16(v.y);
        __nv_bfloat16 h2 = __float2bfloat16(v.z);
        __nv_bfloat16 h3 = __float2bfloat16(v.w);
        __nv_bfloat162 hi01 = __nv_bfloat162(h0, h1);
        __nv_bfloat162 hi23 = __nv_bfloat162(h2, h3);
        __nv_bfloat162 lo01 = __nv_bfloat162(__float2bfloat16(v.x - __bfloat162float(h0)),
                                             __float2bfloat16(v.y - __bfloat162float(h1)));
        __nv_bfloat162 lo23 = __nv_bfloat162(__float2bfloat16(v.z - __bfloat162float(h2)),
                                             __float2bfloat16(v.w - __bfloat162float(h3)));
        uint32_t o = (uint32_t)r * 272u + (uint32_t)c * 8u;
        *reinterpret_cast<uint2*>(smc + S_AH + o) =
            make_uint2(*(uint32_t*)&hi01, *(uint32_t*)&hi23);
        *reinterpret_cast<uint2*>(smc + S_AL + o) =
            make_uint2(*(uint32_t*)&lo01, *(uint32_t*)&lo23);
    }

    const uint32_t lrow = (uint32_t)(lane & 15);
    const uint32_t lkh  = (uint32_t)(lane >> 4) * 16u;
    const uint32_t aoff = ((uint32_t)(wm * 32) + lrow) * 272u + lkh;
    const uint32_t boff = ((uint32_t)(wn * 32) + lrow) * 272u + lkh;

    // per-thread epilogue row metadata (constant across n-tiles)
    const int rbase = m0 + wm * 32 + (lane >> 2);
    float vr[4];   // v[] for rows rbase + {0,8,16,24}
    #pragma unroll
    for (int i = 0; i < 4; i++) {
        int rr = rbase + i * 8;
        vr[i] = (rr < NN) ? __ldg(vrow + rr) : 0.f;
    }

    #pragma unroll 1
    for (int q = 0; q < 4; q++) {
        const int nt = blockIdx.x * 4 + q;

        // ---- stage B tile (hi+lo), 64 n-rows (padded table: always in-bounds) ----
        #pragma unroll
        for (int it = 0; it < 4; it++) {
            int idx = tid + it * 256;
            int r = idx >> 4, c = idx & 15;
            int n = nt * 64 + r;
            uint4 vh = *reinterpret_cast<const uint4*>(Bhi + (size_t)n * 128 + c * 8);
            uint4 vl = *reinterpret_cast<const uint4*>(Blo + (size_t)n * 128 + c * 8);
            uint32_t o = (uint32_t)r * 272u + (uint32_t)c * 16u;
            *reinterpret_cast<uint4*>(smc + S_BH + o) = vh;
            *reinterpret_cast<uint4*>(smc + S_BL + o) = vl;
        }
        __syncthreads();

        float acc[2][4][4];
        #pragma unroll
        for (int i = 0; i < 2; i++)
            #pragma unroll
            for (int j = 0; j < 4; j++)
                #pragma unroll
                for (int p = 0; p < 4; p++) acc[i][j][p] = 0.f;

        #pragma unroll
        for (int p = 0; p < 3; p++) {
            const uint32_t abase = sb + (p == 2 ? S_AL : S_AH) + aoff;
            const uint32_t bbase = sb + (p == 1 ? S_BL : S_BH) + boff;
            #pragma unroll
            for (int ks = 0; ks < 8; ks++) {
                const uint32_t ko = (uint32_t)ks * 32u;
                uint32_t a[2][4];
                LDSM4(a[0][0], a[0][1], a[0][2], a[0][3], abase + ko);
                LDSM4(a[1][0], a[1][1], a[1][2], a[1][3], abase + ko + 16u * 272u);
                uint32_t b[2][4];
                LDSM4(b[0][0], b[0][1], b[0][2], b[0][3], bbase + ko);
                LDSM4(b[1][0], b[1][1], b[1][2], b[1][3], bbase + ko + 16u * 272u);
                #pragma unroll
                for (int i = 0; i < 2; i++) {
                    #pragma unroll
                    for (int jj = 0; jj < 2; jj++) {
                        MMA16816(acc[i][jj * 2][0], acc[i][jj * 2][1],
                                 acc[i][jj * 2][2], acc[i][jj * 2][3],
                                 a[i][0], a[i][1], a[i][2], a[i][3], b[jj][0], b[jj][2]);
                        MMA16816(acc[i][jj * 2 + 1][0], acc[i][jj * 2 + 1][1],
                                 acc[i][jj * 2 + 1][2], acc[i][jj * 2 + 1][3],
                                 a[i][0], a[i][1], a[i][2], a[i][3], b[jj][1], b[jj][3]);
                    }
                }
            }
        }

        // ---- epilogue: out = acc + v[r]*c1[col] + c0[col] ----
        const int cbase = nt * 64 + wn * 32 + (lane & 3) * 2;
        #pragma unroll
        for (int i = 0; i < 2; i++) {
            const int r0 = rbase + i * 16;
            const int r1 = r0 + 8;
            const float v0 = vr[i * 2], v1 = vr[i * 2 + 1];
            #pragma unroll
            for (int j = 0; j < 4; j++) {
                const int col = cbase + j * 8;
                if (col >= NU) continue;
                float c1x = __ldg(c1v + col),     c1y = __ldg(c1v + col + 1);
                float c0x = __ldg(c0v + col),     c0y = __ldg(c0v + col + 1);
                if (r0 < NN) {
                    float2 o = make_float2(acc[i][j][0] + v0 * c1x + c0x,
                                           acc[i][j][1] + v0 * c1y + c0y);
                    *reinterpret_cast<float2*>(C + (size_t)r0 * NU + col) = o;
                }
                if (r1 < NN) {
                    float2 o = make_float2(acc[i][j][2] + v1 * c1x + c0x,
                                           acc[i][j][3] + v1 * c1y + c0y);
                    *reinterpret_cast<float2*>(C + (size_t)r1 * NU + col) = o;
                }
            }
        }
        __syncthreads();   // all warps done with B smem before next q overwrites
    }
}

// ---------------- launch ----------------
extern "C" void kernel_launch(void* const* d_in, const int* in_sizes, int n_in,
                              void* d_out, int out_size) {
    const void*  ei  = d_in[0];
    const float* ew  = (const float*)d_in[1];
    const float* emb = (const float*)d_in[2];
    const float* W1  = (const float*)d_in[3];
    const float* b1  = (const float*)d_in[4];
    const float* W2  = (const float*)d_in[5];
    const float* b2  = (const float*)d_in[6];
    const float* Wp  = (const float*)d_in[7];
    const float* bp  = (const float*)d_in[8];
    float* out = (float*)d_out;

    float *bufA, *bufB, *deg, *v, *nrm, *w2p, *wc, *c1, *c0;
    __nv_bfloat16 *wcthi, *wctlo;
    cudaGetSymbolAddress((void**)&bufA,  g_bufA);
    cudaGetSymbolAddress((void**)&bufB,  g_bufB);
    cudaGetSymbolAddress((void**)&deg,   g_deg);
    cudaGetSymbolAddress((void**)&v,     g_v);
    cudaGetSymbolAddress((void**)&nrm,   g_norm);
    cudaGetSymbolAddress((void**)&w2p,   g_W2p);
    cudaGetSymbolAddress((void**)&wc,    g_Wc);
    cudaGetSymbolAddress((void**)&c1,    g_c1);
    cudaGetSymbolAddress((void**)&c0,    g_c0);
    cudaGetSymbolAddress((void**)&wcthi, g_Wcthi);
    cudaGetSymbolAddress((void**)&wctlo, g_Wctlo);

    cudaFuncSetAttribute(gemm_out, cudaFuncAttributeMaxDynamicSharedMemorySize,
                         GEMM_MMA_SMEM);

    // 1-5: prep (launch #6 = scatter1 for ncu -s 5 -c 1)
    zero_misc_kernel<<<(NZERO + 255) / 256, 256>>>(bufA, bufB, deg, v);          // 1
    sniff_dtype_kernel<<<1, 32>>>((const int*)ei);                               // 2
    deg_kernel<<<(NE + 255) / 256, 256>>>(ei, ew, deg);                          // 3
    dinv_kernel<<<(NN + 255) / 256, 256>>>(deg);                                 // 4
    norm_kernel<<<(NE + 255) / 256, 256>>>(ei, ew, deg, nrm, v);                 // 5

    // 6-7: Z1 = A*X ; Z2 = A*Z1
    scatter_kernel<<<(NE * 32) / 256, 256>>>(ei, nrm, emb, bufA);                // 6 (profiled)
    scatter_kernel<<<(NE * 32) / 256, 256>>>(ei, nrm, bufA, bufB);               // 7

    // 8-11: weight combine + split
    smallgemm_kernel<<<(128 * NU + 255) / 256, 256>>>(W2, Wp, w2p, NU);          // 8
    smallgemm_kernel<<<(128 * NU + 255) / 256, 256>>>(W1, w2p, wc, NU);          // 9
    vec_kernel<<<(NU + 255) / 256, 256>>>(b1, w2p, b2, Wp, bp, c1, c0);          // 10
    split_w_kernel<<<(1024 * 128 + 255) / 256, 256>>>(wc, wcthi, wctlo, NU, 1024); // 11

    // 12: out = Z2 @ Wc + v*c1 + c0
    gemm_out<<<dim3(4, MTILES), 256, GEMM_MMA_SMEM>>>(bufB, wcthi, wctlo, c0, c1, v, out);
}